// round 1
// baseline (speedup 1.0000x reference)
#include <cuda_runtime.h>
#include <cstdint>

// Problem constants: B=2, S=1024, D=2048, F=8192, E=4, K=2
#define TT 2048   // tokens = B*S
#define TD 2048   // d_model
#define TF 8192   // d_ff
#define TE 4      // experts
#define NA 4096   // assignments = TT * K

// ---------------- device scratch (static; no runtime alloc) ----------------
__device__ int   g_counts[TE];
__device__ int   g_fill[TE];
__device__ int   g_offs[TE + 1];
__device__ int   g_eidx[NA];
__device__ float g_gate[NA];
__device__ int   g_rowmap[NA];    // segment row -> assignment id (t*2+k)
__device__ float g_rowgate[NA];   // segment row -> gate value
__device__ float g_H[(size_t)NA * TF];   // 134 MB hidden activations
__device__ float g_Y[(size_t)NA * TD];   // 33.5 MB per-assignment outputs

// ---------------- helpers ----------------
__device__ __forceinline__ uint32_t f2tf(float f) {
    uint32_t u;
    asm("cvt.rna.tf32.f32 %0, %1;" : "=r"(u) : "f"(f));
    return u;
}
__device__ __forceinline__ uint4 cvt4(float4 v) {
    uint4 r;
    r.x = f2tf(v.x); r.y = f2tf(v.y); r.z = f2tf(v.z); r.w = f2tf(v.w);
    return r;
}
__device__ __forceinline__ void mma_tf32(float* c,
                                         uint32_t a0, uint32_t a1, uint32_t a2, uint32_t a3,
                                         uint32_t b0, uint32_t b1) {
    asm volatile(
        "mma.sync.aligned.m16n8k8.row.col.f32.tf32.tf32.f32 "
        "{%0,%1,%2,%3}, {%4,%5,%6,%7}, {%8,%9}, {%0,%1,%2,%3};"
        : "+f"(c[0]), "+f"(c[1]), "+f"(c[2]), "+f"(c[3])
        : "r"(a0), "r"(a1), "r"(a2), "r"(a3), "r"(b0), "r"(b1));
}

// ---------------- routing ----------------
__global__ void zero_kernel() {
    int i = threadIdx.x;
    if (i < TE) { g_counts[i] = 0; g_fill[i] = 0; }
}

__global__ void router_kernel(const float* __restrict__ x, const float* __restrict__ Wr) {
    int gw   = (int)((blockIdx.x * blockDim.x + threadIdx.x) >> 5);  // one warp per token
    int lane = threadIdx.x & 31;
    if (gw >= TT) return;
    const float* xr = x + (size_t)gw * TD;
    float a0 = 0.f, a1 = 0.f, a2 = 0.f, a3 = 0.f;
    for (int d = lane; d < TD; d += 32) {
        float xv = xr[d];
        float4 w = *(const float4*)(Wr + d * 4);
        a0 += xv * w.x; a1 += xv * w.y; a2 += xv * w.z; a3 += xv * w.w;
    }
    #pragma unroll
    for (int o = 16; o; o >>= 1) {
        a0 += __shfl_xor_sync(0xffffffffu, a0, o);
        a1 += __shfl_xor_sync(0xffffffffu, a1, o);
        a2 += __shfl_xor_sync(0xffffffffu, a2, o);
        a3 += __shfl_xor_sync(0xffffffffu, a3, o);
    }
    if (lane == 0) {
        float l[4] = {a0, a1, a2, a3};
        float m = fmaxf(fmaxf(l[0], l[1]), fmaxf(l[2], l[3]));
        float p[4]; float s = 0.f;
        #pragma unroll
        for (int i = 0; i < 4; i++) { p[i] = __expf(l[i] - m); s += p[i]; }
        float inv = 1.0f / s;
        int i0 = 0;
        #pragma unroll
        for (int i = 1; i < 4; i++) if (p[i] > p[i0]) i0 = i;
        int i1 = (i0 == 0) ? 1 : 0;
        #pragma unroll
        for (int i = 0; i < 4; i++) if (i != i0 && p[i] > p[i1]) i1 = i;
        g_eidx[gw * 2]     = i0; g_gate[gw * 2]     = p[i0] * inv;
        g_eidx[gw * 2 + 1] = i1; g_gate[gw * 2 + 1] = p[i1] * inv;
        atomicAdd(&g_counts[i0], 1);
        atomicAdd(&g_counts[i1], 1);
    }
}

__global__ void offsets_kernel() {
    if (threadIdx.x == 0) {
        int s = 0;
        for (int e = 0; e < TE; e++) { g_offs[e] = s; s += g_counts[e]; }
        g_offs[TE] = s;
    }
}

__global__ void scatter_kernel() {
    int a = blockIdx.x * blockDim.x + threadIdx.x;
    if (a >= NA) return;
    int e = g_eidx[a];
    int pos = g_offs[e] + atomicAdd(&g_fill[e], 1);
    g_rowmap[pos]  = a;
    g_rowgate[pos] = g_gate[a];
}

// ---------------- GEMM1: H = silu(Xe*Wg) * (Xe*Wu) ----------------
// Tile 64(M) x 64(N), KB=32 over D. 8 warps (2x4), warp tile 32x16, tf32 mma.
__global__ __launch_bounds__(256, 2) void gemm1_kernel(
    const float* __restrict__ x, const float* __restrict__ Wg, const float* __restrict__ Wu) {
    __shared__ __align__(16) uint32_t As[64][36];
    __shared__ __align__(16) uint32_t Bgs[32][72];
    __shared__ __align__(16) uint32_t Bus[32][72];

    const int e    = blockIdx.z;
    const int cnt  = g_counts[e];
    const int row0 = blockIdx.x * 64;
    if (row0 >= cnt) return;
    const int segbase = g_offs[e];
    const int f0   = blockIdx.y * 64;

    const int tid  = threadIdx.x;
    const int lane = tid & 31;
    const int warp = tid >> 5;
    const int grp  = lane >> 2;   // 0..7
    const int t4   = lane & 3;    // 0..3
    const int wm   = warp & 1;    // 2 warp rows (32 each)
    const int wn   = warp >> 1;   // 4 warp cols (16 each)

    // A (gathered token rows): thread loads rows rA and rA+32, float4 at col c8
    const int rA = tid >> 3;
    const int c8 = (tid & 7) << 2;
    const float* ap0 = nullptr;
    const float* ap1 = nullptr;
    if (row0 + rA < cnt)
        ap0 = x + (size_t)(g_rowmap[segbase + row0 + rA] >> 1) * TD + c8;
    if (row0 + rA + 32 < cnt)
        ap1 = x + (size_t)(g_rowmap[segbase + row0 + rA + 32] >> 1) * TD + c8;

    // B: rows kB and kB+16, float4 at col c16
    const int kB  = tid >> 4;
    const int c16 = (tid & 15) << 2;
    const float* bgp = Wg + (size_t)e * TD * TF + (size_t)kB * TF + f0 + c16;
    const float* bup = Wu + (size_t)e * TD * TF + (size_t)kB * TF + f0 + c16;

    float accG[2][2][4], accU[2][2][4];
    #pragma unroll
    for (int i = 0; i < 2; i++)
        #pragma unroll
        for (int j = 0; j < 2; j++)
            #pragma unroll
            for (int q = 0; q < 4; q++) { accG[i][j][q] = 0.f; accU[i][j][q] = 0.f; }

    for (int kb = 0; kb < TD; kb += 32) {
        float4 av0 = ap0 ? *(const float4*)(ap0 + kb) : make_float4(0.f, 0.f, 0.f, 0.f);
        float4 av1 = ap1 ? *(const float4*)(ap1 + kb) : make_float4(0.f, 0.f, 0.f, 0.f);
        float4 gv0 = *(const float4*)(bgp + (size_t)kb * TF);
        float4 gv1 = *(const float4*)(bgp + (size_t)(kb + 16) * TF);
        float4 uv0 = *(const float4*)(bup + (size_t)kb * TF);
        float4 uv1 = *(const float4*)(bup + (size_t)(kb + 16) * TF);
        __syncthreads();
        *(uint4*)&As[rA][c8]        = cvt4(av0);
        *(uint4*)&As[rA + 32][c8]   = cvt4(av1);
        *(uint4*)&Bgs[kB][c16]      = cvt4(gv0);
        *(uint4*)&Bgs[kB + 16][c16] = cvt4(gv1);
        *(uint4*)&Bus[kB][c16]      = cvt4(uv0);
        *(uint4*)&Bus[kB + 16][c16] = cvt4(uv1);
        __syncthreads();

        #pragma unroll
        for (int ks = 0; ks < 4; ks++) {
            const int kk = ks * 8 + t4;
            uint32_t af[2][4];
            #pragma unroll
            for (int mi = 0; mi < 2; mi++) {
                const int r = wm * 32 + mi * 16 + grp;
                af[mi][0] = As[r][kk];
                af[mi][1] = As[r + 8][kk];
                af[mi][2] = As[r][kk + 4];
                af[mi][3] = As[r + 8][kk + 4];
            }
            #pragma unroll
            for (int ni = 0; ni < 2; ni++) {
                const int c = wn * 16 + ni * 8 + grp;
                uint32_t bg0 = Bgs[kk][c], bg1 = Bgs[kk + 4][c];
                uint32_t bu0 = Bus[kk][c], bu1 = Bus[kk + 4][c];
                #pragma unroll
                for (int mi = 0; mi < 2; mi++) {
                    mma_tf32(accG[mi][ni], af[mi][0], af[mi][1], af[mi][2], af[mi][3], bg0, bg1);
                    mma_tf32(accU[mi][ni], af[mi][0], af[mi][1], af[mi][2], af[mi][3], bu0, bu1);
                }
            }
        }
    }

    // epilogue: h = g * u * sigmoid(g) -> g_H
    #pragma unroll
    for (int mi = 0; mi < 2; mi++) {
        #pragma unroll
        for (int ni = 0; ni < 2; ni++) {
            const int rl = wm * 32 + mi * 16 + grp;
            const int c  = f0 + wn * 16 + ni * 8 + t4 * 2;
            int gr = row0 + rl;
            if (gr < cnt) {
                float g0 = accG[mi][ni][0], u0 = accU[mi][ni][0];
                float g1 = accG[mi][ni][1], u1 = accU[mi][ni][1];
                float2 h;
                h.x = __fdividef(g0 * u0, 1.0f + __expf(-g0));
                h.y = __fdividef(g1 * u1, 1.0f + __expf(-g1));
                *(float2*)&g_H[(size_t)(segbase + gr) * TF + c] = h;
            }
            gr = row0 + rl + 8;
            if (gr < cnt) {
                float g0 = accG[mi][ni][2], u0 = accU[mi][ni][2];
                float g1 = accG[mi][ni][3], u1 = accU[mi][ni][3];
                float2 h;
                h.x = __fdividef(g0 * u0, 1.0f + __expf(-g0));
                h.y = __fdividef(g1 * u1, 1.0f + __expf(-g1));
                *(float2*)&g_H[(size_t)(segbase + gr) * TF + c] = h;
            }
        }
    }
}

// ---------------- GEMM2: Y = gate * (H * Wd), scattered to (t,k) slots ----------------
__global__ __launch_bounds__(256, 2) void gemm2_kernel(const float* __restrict__ Wd) {
    __shared__ __align__(16) uint32_t As[64][36];
    __shared__ __align__(16) uint32_t Bs[32][72];

    const int e    = blockIdx.z;
    const int cnt  = g_counts[e];
    const int row0 = blockIdx.x * 64;
    if (row0 >= cnt) return;
    const int segbase = g_offs[e];
    const int n0   = blockIdx.y * 64;

    const int tid  = threadIdx.x;
    const int lane = tid & 31;
    const int warp = tid >> 5;
    const int grp  = lane >> 2;
    const int t4   = lane & 3;
    const int wm   = warp & 1;
    const int wn   = warp >> 1;

    const int rA = tid >> 3;
    const int c8 = (tid & 7) << 2;
    const float* ap0 = nullptr;
    const float* ap1 = nullptr;
    if (row0 + rA < cnt)
        ap0 = g_H + (size_t)(segbase + row0 + rA) * TF + c8;
    if (row0 + rA + 32 < cnt)
        ap1 = g_H + (size_t)(segbase + row0 + rA + 32) * TF + c8;

    const int kB  = tid >> 4;
    const int c16 = (tid & 15) << 2;
    const float* bdp = Wd + (size_t)e * TF * TD + (size_t)kB * TD + n0 + c16;

    float acc[2][2][4];
    #pragma unroll
    for (int i = 0; i < 2; i++)
        #pragma unroll
        for (int j = 0; j < 2; j++)
            #pragma unroll
            for (int q = 0; q < 4; q++) acc[i][j][q] = 0.f;

    for (int kb = 0; kb < TF; kb += 32) {
        float4 av0 = ap0 ? *(const float4*)(ap0 + kb) : make_float4(0.f, 0.f, 0.f, 0.f);
        float4 av1 = ap1 ? *(const float4*)(ap1 + kb) : make_float4(0.f, 0.f, 0.f, 0.f);
        float4 bv0 = *(const float4*)(bdp + (size_t)kb * TD);
        float4 bv1 = *(const float4*)(bdp + (size_t)(kb + 16) * TD);
        __syncthreads();
        *(uint4*)&As[rA][c8]       = cvt4(av0);
        *(uint4*)&As[rA + 32][c8]  = cvt4(av1);
        *(uint4*)&Bs[kB][c16]      = cvt4(bv0);
        *(uint4*)&Bs[kB + 16][c16] = cvt4(bv1);
        __syncthreads();

        #pragma unroll
        for (int ks = 0; ks < 4; ks++) {
            const int kk = ks * 8 + t4;
            uint32_t af[2][4];
            #pragma unroll
            for (int mi = 0; mi < 2; mi++) {
                const int r = wm * 32 + mi * 16 + grp;
                af[mi][0] = As[r][kk];
                af[mi][1] = As[r + 8][kk];
                af[mi][2] = As[r][kk + 4];
                af[mi][3] = As[r + 8][kk + 4];
            }
            #pragma unroll
            for (int ni = 0; ni < 2; ni++) {
                const int c = wn * 16 + ni * 8 + grp;
                uint32_t b0 = Bs[kk][c], b1 = Bs[kk + 4][c];
                #pragma unroll
                for (int mi = 0; mi < 2; mi++)
                    mma_tf32(acc[mi][ni], af[mi][0], af[mi][1], af[mi][2], af[mi][3], b0, b1);
            }
        }
    }

    #pragma unroll
    for (int mi = 0; mi < 2; mi++) {
        #pragma unroll
        for (int ni = 0; ni < 2; ni++) {
            const int rl = wm * 32 + mi * 16 + grp;
            const int c  = n0 + wn * 16 + ni * 8 + t4 * 2;
            int gr = row0 + rl;
            if (gr < cnt) {
                int   a = g_rowmap[segbase + gr];
                float w = g_rowgate[segbase + gr];
                float2 v; v.x = w * acc[mi][ni][0]; v.y = w * acc[mi][ni][1];
                *(float2*)&g_Y[(size_t)a * TD + c] = v;
            }
            gr = row0 + rl + 8;
            if (gr < cnt) {
                int   a = g_rowmap[segbase + gr];
                float w = g_rowgate[segbase + gr];
                float2 v; v.x = w * acc[mi][ni][2]; v.y = w * acc[mi][ni][3];
                *(float2*)&g_Y[(size_t)a * TD + c] = v;
            }
        }
    }
}

// ---------------- combine: out[t] = Y[t,0] + Y[t,1] ----------------
__global__ void combine_kernel(float* __restrict__ out) {
    int i = blockIdx.x * blockDim.x + threadIdx.x;   // TT*TD = 4194304
    if (i >= TT * TD) return;
    int t = i >> 11;      // / TD
    int d = i & (TD - 1);
    out[i] = g_Y[(size_t)(2 * t) * TD + d] + g_Y[(size_t)(2 * t + 1) * TD + d];
}

// ---------------- launch ----------------
extern "C" void kernel_launch(void* const* d_in, const int* in_sizes, int n_in,
                              void* d_out, int out_size) {
    const float* x  = (const float*)d_in[0];
    const float* Wr = (const float*)d_in[1];
    const float* Wg = (const float*)d_in[2];
    const float* Wu = (const float*)d_in[3];
    const float* Wd = (const float*)d_in[4];
    float* out = (float*)d_out;

    zero_kernel<<<1, 32>>>();
    router_kernel<<<TT / 8, 256>>>(x, Wr);     // one warp per token
    offsets_kernel<<<1, 1>>>();
    scatter_kernel<<<NA / 256, 256>>>();

    dim3 grid1(32, TF / 64, TE);               // row-tile fastest: B-panel reuse via L2
    gemm1_kernel<<<grid1, 256>>>(x, Wg, Wu);

    dim3 grid2(32, TD / 64, TE);
    gemm2_kernel<<<grid2, 256>>>(Wd);

    combine_kernel<<<(TT * TD) / 256, 256>>>(out);
}